// round 14
// baseline (speedup 1.0000x reference)
#include <cuda_runtime.h>
#include <cuda_fp16.h>
#include <math.h>

// Problem constants (fixed by the reference)
#define NN 100000   // nodes
#define EE 1600000  // edges
#define HH 128      // channels
#define GG 64       // graphs
#define PCH 8       // pool chunks per graph

// ---------------- static device scratch (no allocations allowed) ----------
// fp16 activation ping-pong (fp32 math, fp16 storage), padded +128 rows so
// the GEMM needs no bounds checks (pad rows stay zero forever).
__device__ __align__(16) __half g_ah[(size_t)(NN + 128) * HH];
__device__ __align__(16) __half g_th[(size_t)(NN + 128) * HH];
// repacked W B-fragments, 3 layers, layout [layer][kc][lane][nt]
__device__ __align__(16) uint2  g_bw[3 * 8 * 32 * 16];
__device__ float g_dinv[NN];              // deg -> d^{-1/2} (in place)
// CSR (destination-sorted) adjacency, built once
__device__ int   g_cnt[NN];               // int in-degree
__device__ int   g_off[NN + 1];           // exclusive scan of cnt
__device__ int   g_fill[NN];              // slot fill counters
__device__ int   g_bsum[256];             // block sums for scan
__device__ __align__(8) int2 g_adj[EE];   // {src, w-bits}, sorted by dst
__device__ float g_part[GG * PCH];        // pool partial dots
__device__ int   g_ei_is64;               // dtype flags (auto-detected)
__device__ int   g_b_is64;

// ---------------- x -> fp16 conversion (layer-1 GEMM input) ----------------
__global__ void cvtx_k(const float* __restrict__ x)
{
    int i = blockIdx.x * blockDim.x + threadIdx.x;   // over N*H/8 uint4
    if (i >= NN * HH / 8) return;
    const float4* p = (const float4*)x + 2 * (size_t)i;
    float4 u0 = p[0], u1 = p[1];
    union { __half2 h[4]; uint4 u; } cv;
    cv.h[0] = __float22half2_rn(make_float2(u0.x, u0.y));
    cv.h[1] = __float22half2_rn(make_float2(u0.z, u0.w));
    cv.h[2] = __float22half2_rn(make_float2(u1.x, u1.y));
    cv.h[3] = __float22half2_rn(make_float2(u1.z, u1.w));
    ((uint4*)g_ah)[i] = cv.u;
}

// ---------------- W -> B-fragment repack (all 3 layers at once) ------------
// B fragment for mma.m16n8k16.row.col (B = W[k][n], col-major 16x8 frag):
//   lane: b0=B[t2][g], b1=B[t2+1][g], b2=B[t2+8][g], b3=B[t2+9][g]
//   with t2=(lane%4)*2, g=lane/4;  reg0=(b0,b1), reg1=(b2,b3)
// Layout: g_bw[(((L*8)+kc)*32+lane)*16 + nt]  (nt contiguous -> uint4 loads)
__global__ void repack_k(const float* __restrict__ W0,
                         const float* __restrict__ W1,
                         const float* __restrict__ W2)
{
    int tid = blockIdx.x * blockDim.x + threadIdx.x;   // 0..12287
    if (tid >= 3 * 8 * 32 * 16) return;
    int nt   = tid & 15;
    int lane = (tid >> 4) & 31;
    int kc   = (tid >> 9) & 7;
    int L    = tid >> 12;
    const float* W = (L == 0) ? W0 : (L == 1) ? W1 : W2;
    int k0 = kc * 16 + (lane & 3) * 2;
    int n  = nt * 8 + (lane >> 2);
    float f0 = W[(k0 + 0) * 128 + n];
    float f1 = W[(k0 + 1) * 128 + n];
    float f2 = W[(k0 + 8) * 128 + n];
    float f3 = W[(k0 + 9) * 128 + n];
    union { __half2 h; unsigned u; } lo, hi;
    lo.h = __float22half2_rn(make_float2(f0, f1));
    hi.h = __float22half2_rn(make_float2(f2, f3));
    g_bw[tid] = make_uint2(lo.u, hi.u);
}

// ---------------- init + dtype detection (fused) ----------------------------
// int64 payloads with values < 2^31 have all odd 32-bit words zero; int32
// payloads essentially never do. Sampled offsets are in-bounds either way.
__global__ void init_k(const int* __restrict__ ei32,
                       const int* __restrict__ b32)
{
    int i = blockIdx.x * blockDim.x + threadIdx.x;
    if (i < NN) { g_dinv[i] = 1.0f; g_cnt[i] = 0; g_fill[i] = 0; }
    if (blockIdx.x == 0) {
        int tid = threadIdx.x;                   // 256 threads
        int je = 1 + 12500 * tid;                // odd words across [1, 2*EE)
        int ei_nz = (ei32[je] != 0);
        int jb = 50001 + 194 * tid;              // odd words, upper half of N
        int b_nz = (b32[jb] != 0);
        int any_ei = __syncthreads_or(ei_nz);
        int any_b  = __syncthreads_or(b_nz);
        if (tid == 0) {
            g_ei_is64 = (any_ei == 0);
            g_b_is64  = (any_b  == 0);
        }
    }
}

// ---------------- edge prep: weighted degree + int in-degree ---------------
__global__ void prep_k(const void* __restrict__ ei,
                       const float* __restrict__ ew) {
    int e = blockIdx.x * blockDim.x + threadIdx.x;
    if (e >= EE) return;
    int c;
    if (g_ei_is64) c = (int)((const long long*)ei)[EE + e];
    else           c = ((const int*)ei)[EE + e];
    atomicAdd(&g_dinv[c], ew[e]);           // weighted in-degree
    atomicAdd(&g_cnt[c], 1);                // integer in-degree (for CSR)
}

// ---------------- exclusive scan of g_cnt -> g_off (+ fused dinv) ----------
#define SCAN_B 512
__global__ void scan1_k() {      // per-block exclusive scan + block totals
    __shared__ int sm[SCAN_B];
    int t = threadIdx.x;
    int idx = blockIdx.x * SCAN_B + t;
    int v = (idx < NN) ? g_cnt[idx] : 0;
    sm[t] = v;
    if (idx < NN) {
        float d = g_dinv[idx];
        g_dinv[idx] = (d > 0.0f) ? rsqrtf(d) : 0.0f;
    }
    __syncthreads();
#pragma unroll
    for (int o = 1; o < SCAN_B; o <<= 1) {
        int x = (t >= o) ? sm[t - o] : 0;
        __syncthreads();
        sm[t] += x;
        __syncthreads();
    }
    if (idx < NN) g_off[idx] = sm[t] - v;        // exclusive
    if (t == SCAN_B - 1) g_bsum[blockIdx.x] = sm[t];
}
__global__ void scan2_k(int nblk) {  // single block: scan block totals
    __shared__ int sm[256];
    int t = threadIdx.x;
    int v = (t < nblk) ? g_bsum[t] : 0;
    sm[t] = v;
    __syncthreads();
#pragma unroll
    for (int o = 1; o < 256; o <<= 1) {
        int x = (t >= o) ? sm[t - o] : 0;
        __syncthreads();
        sm[t] += x;
        __syncthreads();
    }
    if (t < nblk) g_bsum[t] = sm[t] - v;         // exclusive
}
__global__ void scan3_k() {
    int idx = blockIdx.x * SCAN_B + threadIdx.x;
    if (idx < NN) g_off[idx] += g_bsum[blockIdx.x];
    if (idx == 0) g_off[NN] = EE;
}

// ---------------- build sorted adjacency (counting-sort fill) --------------
// decodes edge_index directly (no intermediate row/col arrays)
__global__ void build_k(const void* __restrict__ ei,
                        const float* __restrict__ ew) {
    int e = blockIdx.x * blockDim.x + threadIdx.x;
    if (e >= EE) return;
    int r, c;
    if (g_ei_is64) {
        const long long* p = (const long long*)ei;
        r = (int)p[e]; c = (int)p[EE + e];
    } else {
        const int* p = (const int*)ei;
        r = p[e]; c = p[EE + e];
    }
    int pos = g_off[c] + atomicAdd(&g_fill[c], 1);
    float w = g_dinv[r] * ew[e] * g_dinv[c];
    g_adj[pos] = make_int2(r, __float_as_int(w));
}

// ---------------- tensor-core GEMM: g_th = g_ah[N,128] @ W[128,128] --------
// mma.sync.m16n8k16 (fp16 in, fp32 accum). 256 threads = 8 warps:
// 4 m-warps x 2 n-warps; warp tile m32 x n64 (2 MMAs per B-fragment load);
// block tile 128x128, grid 782. Buffers padded -> no bounds checks.
__global__ void __launch_bounds__(256, 2)
gemm_tc(int L)
{
    const int lane = threadIdx.x & 31;
    const int warp = threadIdx.x >> 5;
    const int wm = warp & 3;            // 0..3
    const int wn = warp >> 2;           // 0..1
    const int rowbase = blockIdx.x * 128 + wm * 32;

    const int g  = lane >> 2;           // 0..7
    const int t2 = (lane & 3) * 2;      // 0,2,4,6

    float c0[8][4], c1[8][4];           // two m16 frags x 8 n-tiles
#pragma unroll
    for (int nt = 0; nt < 8; ++nt)
#pragma unroll
        for (int j = 0; j < 4; ++j) { c0[nt][j] = 0.0f; c1[nt][j] = 0.0f; }

    const __half* pA0 = g_ah + (size_t)(rowbase + g)      * HH;
    const __half* pA1 = g_ah + (size_t)(rowbase + g + 8)  * HH;
    const __half* pA2 = g_ah + (size_t)(rowbase + g + 16) * HH;
    const __half* pA3 = g_ah + (size_t)(rowbase + g + 24) * HH;

    // B base for this lane: [(L*8+kc)*32+lane]*16 + wn*8, nt 0..7 contiguous
    const uint4* bbase =
        (const uint4*)(g_bw + ((size_t)(L * 8) * 32 + lane) * 16 + wn * 8);

#pragma unroll
    for (int kc = 0; kc < 8; ++kc) {
        int off = kc * 16 + t2;
        unsigned a00 = *(const unsigned*)(pA0 + off);
        unsigned a01 = *(const unsigned*)(pA1 + off);
        unsigned a02 = *(const unsigned*)(pA0 + off + 8);
        unsigned a03 = *(const unsigned*)(pA1 + off + 8);
        unsigned a10 = *(const unsigned*)(pA2 + off);
        unsigned a11 = *(const unsigned*)(pA3 + off);
        unsigned a12 = *(const unsigned*)(pA2 + off + 8);
        unsigned a13 = *(const unsigned*)(pA3 + off + 8);
        // 4 x uint4 = 8 B fragments (nt 0..7).
        // kc stride = 32 lanes * 16 nt = 512 uint2 = 256 uint4.
        const uint4* bp = bbase + (size_t)kc * 256;
        uint4 bv0 = __ldg(bp + 0);
        uint4 bv1 = __ldg(bp + 1);
        uint4 bv2 = __ldg(bp + 2);
        uint4 bv3 = __ldg(bp + 3);
        unsigned bx[8], by[8];
        bx[0] = bv0.x; by[0] = bv0.y; bx[1] = bv0.z; by[1] = bv0.w;
        bx[2] = bv1.x; by[2] = bv1.y; bx[3] = bv1.z; by[3] = bv1.w;
        bx[4] = bv2.x; by[4] = bv2.y; bx[5] = bv2.z; by[5] = bv2.w;
        bx[6] = bv3.x; by[6] = bv3.y; bx[7] = bv3.z; by[7] = bv3.w;
#pragma unroll
        for (int nt = 0; nt < 8; ++nt) {
            asm volatile(
                "mma.sync.aligned.m16n8k16.row.col.f32.f16.f16.f32 "
                "{%0,%1,%2,%3}, {%4,%5,%6,%7}, {%8,%9}, {%0,%1,%2,%3};"
                : "+f"(c0[nt][0]), "+f"(c0[nt][1]),
                  "+f"(c0[nt][2]), "+f"(c0[nt][3])
                : "r"(a00), "r"(a01), "r"(a02), "r"(a03),
                  "r"(bx[nt]), "r"(by[nt]));
            asm volatile(
                "mma.sync.aligned.m16n8k16.row.col.f32.f16.f16.f32 "
                "{%0,%1,%2,%3}, {%4,%5,%6,%7}, {%8,%9}, {%0,%1,%2,%3};"
                : "+f"(c1[nt][0]), "+f"(c1[nt][1]),
                  "+f"(c1[nt][2]), "+f"(c1[nt][3])
                : "r"(a10), "r"(a11), "r"(a12), "r"(a13),
                  "r"(bx[nt]), "r"(by[nt]));
        }
    }

    // epilogue: fp16 stores (padded g_th -> no bounds checks)
    const size_t r0 = (size_t)(rowbase + g) * HH;
#pragma unroll
    for (int nt = 0; nt < 8; ++nt) {
        int colb = (wn * 8 + nt) * 8 + t2;
        union { __half2 h; unsigned u; } v;
        v.h = __float22half2_rn(make_float2(c0[nt][0], c0[nt][1]));
        *(unsigned*)(g_th + r0 + colb) = v.u;
        v.h = __float22half2_rn(make_float2(c0[nt][2], c0[nt][3]));
        *(unsigned*)(g_th + r0 + 8 * HH + colb) = v.u;
        v.h = __float22half2_rn(make_float2(c1[nt][0], c1[nt][1]));
        *(unsigned*)(g_th + r0 + 16 * HH + colb) = v.u;
        v.h = __float22half2_rn(make_float2(c1[nt][2], c1[nt][3]));
        *(unsigned*)(g_th + r0 + 24 * HH + colb) = v.u;
    }
}

// ---------------- fused aggregation (gather, no atomics) -------------------
// acc = bias + dinv[n]^2 * th[n] + sum_{e in in(n)} w[e] * th[src[e]]  (fp32)
// g_ah[n] = relu(acc) fp16. One warp per node; lane l owns channels [4l,4l+4).
__global__ void __launch_bounds__(256)
agg_k(const float* __restrict__ bias)
{
    int warp = (blockIdx.x * blockDim.x + threadIdx.x) >> 5;
    if (warp >= NN) return;
    int lane = threadIdx.x & 31;

    float d = g_dinv[warp];
    float s = d * d;
    float4 acc = ((const float4*)bias)[lane];
    {
        uint2 q = *((const uint2*)(g_th + (size_t)warp * HH) + lane);
        float2 f0 = __half22float2(*(const __half2*)&q.x);
        float2 f1 = __half22float2(*(const __half2*)&q.y);
        acc.x = fmaf(f0.x, s, acc.x); acc.y = fmaf(f0.y, s, acc.y);
        acc.z = fmaf(f1.x, s, acc.z); acc.w = fmaf(f1.y, s, acc.w);
    }

    int k   = g_off[warp];
    int end = g_off[warp + 1];

    for (; k + 16 <= end; k += 16) {
        int2 a[16]; uint2 q[16];
#pragma unroll
        for (int u = 0; u < 16; ++u) a[u] = __ldg(&g_adj[k + u]);
#pragma unroll
        for (int u = 0; u < 16; ++u)
            q[u] = __ldg((const uint2*)(g_th + (size_t)a[u].x * HH) + lane);
#pragma unroll
        for (int u = 0; u < 16; ++u) {
            float w = __int_as_float(a[u].y);
            float2 f0 = __half22float2(*(const __half2*)&q[u].x);
            float2 f1 = __half22float2(*(const __half2*)&q[u].y);
            acc.x = fmaf(f0.x, w, acc.x);
            acc.y = fmaf(f0.y, w, acc.y);
            acc.z = fmaf(f1.x, w, acc.z);
            acc.w = fmaf(f1.y, w, acc.w);
        }
    }
    for (; k + 4 <= end; k += 4) {
        int2 a[4]; uint2 q[4];
#pragma unroll
        for (int u = 0; u < 4; ++u) a[u] = __ldg(&g_adj[k + u]);
#pragma unroll
        for (int u = 0; u < 4; ++u)
            q[u] = __ldg((const uint2*)(g_th + (size_t)a[u].x * HH) + lane);
#pragma unroll
        for (int u = 0; u < 4; ++u) {
            float w = __int_as_float(a[u].y);
            float2 f0 = __half22float2(*(const __half2*)&q[u].x);
            float2 f1 = __half22float2(*(const __half2*)&q[u].y);
            acc.x = fmaf(f0.x, w, acc.x);
            acc.y = fmaf(f0.y, w, acc.y);
            acc.z = fmaf(f1.x, w, acc.z);
            acc.w = fmaf(f1.y, w, acc.w);
        }
    }
    for (; k < end; ++k) {
        int2 a = __ldg(&g_adj[k]);
        float w = __int_as_float(a.y);
        uint2 q = __ldg((const uint2*)(g_th + (size_t)a.x * HH) + lane);
        float2 f0 = __half22float2(*(const __half2*)&q.x);
        float2 f1 = __half22float2(*(const __half2*)&q.y);
        acc.x = fmaf(f0.x, w, acc.x); acc.y = fmaf(f0.y, w, acc.y);
        acc.z = fmaf(f1.x, w, acc.z); acc.w = fmaf(f1.y, w, acc.w);
    }

    acc.x = fmaxf(acc.x, 0.0f); acc.y = fmaxf(acc.y, 0.0f);
    acc.z = fmaxf(acc.z, 0.0f); acc.w = fmaxf(acc.w, 0.0f);
    union { __half2 h[2]; uint2 u; } cv;
    cv.h[0] = __float22half2_rn(make_float2(acc.x, acc.y));
    cv.h[1] = __float22half2_rn(make_float2(acc.z, acc.w));
    *((uint2*)(g_ah + (size_t)warp * HH) + lane) = cv.u;
}

// ---------------- two-stage pool + final linear (atomic-free) --------------
__device__ __forceinline__ int lower_bound_batch(const void* batch, int tgt)
{
    int lo = 0, hi = NN;
    while (lo < hi) {
        int mid = (lo + hi) >> 1;
        long long v = g_b_is64 ? ((const long long*)batch)[mid]
                               : (long long)((const int*)batch)[mid];
        if (v < tgt) lo = mid + 1; else hi = mid;
    }
    return lo;
}

// stage 1: 512 blocks = 64 graphs x 8 chunks; partial dot of channel sums
// with lin_w over a row sub-range (linear, so chunk partials sum exactly).
__global__ void pool1_k(const void* __restrict__ batch,
                        const float* __restrict__ lw)
{
    int g  = blockIdx.x >> 3;        // graph
    int ch = blockIdx.x & 7;         // chunk
    int t  = threadIdx.x;            // 128 threads = channel
    __shared__ int se[2];
    if (t == 0) se[0] = lower_bound_batch(batch, g);
    if (t == 1) se[1] = lower_bound_batch(batch, g + 1);
    __syncthreads();
    int s = se[0], len = se[1] - se[0];
    int c0 = s + (int)(((long long)len * ch) >> 3);
    int c1 = s + (int)(((long long)len * (ch + 1)) >> 3);

    float sum = 0.0f;
    int r = c0;
    for (; r + 4 <= c1; r += 4) {
        sum += __half2float(g_ah[(size_t)(r + 0) * HH + t]);
        sum += __half2float(g_ah[(size_t)(r + 1) * HH + t]);
        sum += __half2float(g_ah[(size_t)(r + 2) * HH + t]);
        sum += __half2float(g_ah[(size_t)(r + 3) * HH + t]);
    }
    for (; r < c1; ++r)
        sum += __half2float(g_ah[(size_t)r * HH + t]);

    float v = sum * lw[t];
#pragma unroll
    for (int o = 16; o > 0; o >>= 1)
        v += __shfl_down_sync(0xffffffffu, v, o);
    __shared__ float sm[4];
    if ((t & 31) == 0) sm[t >> 5] = v;
    __syncthreads();
    if (t == 0) g_part[blockIdx.x] = sm[0] + sm[1] + sm[2] + sm[3];
}

// stage 2: combine chunk partials, divide by node count, add bias.
__global__ void final_k(const void* __restrict__ batch,
                        const float* __restrict__ lb,
                        float* __restrict__ out)
{
    int g = threadIdx.x;             // 64 threads
    if (g >= GG) return;
    int s = lower_bound_batch(batch, g);
    int e = lower_bound_batch(batch, g + 1);
    float sum = 0.0f;
#pragma unroll
    for (int c = 0; c < PCH; ++c) sum += g_part[g * PCH + c];
    out[g] = sum / fmaxf((float)(e - s), 1.0f) + lb[0];
}

// ---------------- launcher --------------------------------------------------
extern "C" void kernel_launch(void* const* d_in, const int* in_sizes, int n_in,
                              void* d_out, int out_size)
{
    // Locate inputs by element count (robust to metadata ordering).
    const float* x = nullptr;
    const float* ew = nullptr;
    const void*  ei = nullptr;     // int32 or int64 (auto-detected on device)
    const void*  batch = nullptr;  // int32 or int64
    const float* Wm[3] = {nullptr, nullptr, nullptr};
    const float* v128[4] = {nullptr, nullptr, nullptr, nullptr}; // b1,b2,b3,lin_w
    const float* linb = nullptr;
    int wi = 0, bi = 0;
    for (int i = 0; i < n_in; ++i) {
        int s = in_sizes[i];
        if      (s == NN * HH)  x = (const float*)d_in[i];
        else if (s == EE)       ew = (const float*)d_in[i];
        else if (s == 2 * EE)   ei = d_in[i];
        else if (s == NN)       batch = d_in[i];
        else if (s == HH * HH)  { if (wi < 3) Wm[wi++] = (const float*)d_in[i]; }
        else if (s == HH)       { if (bi < 4) v128[bi++] = (const float*)d_in[i]; }
        else if (s == 1)        linb = (const float*)d_in[i];
    }
    const float* lw = v128[3];
    float* out = (float*)d_out;

    const int TB = 256;
    const int gN  = (NN + TB - 1) / TB;
    const int gE  = (EE + TB - 1) / TB;
    const int gCv = (NN * HH / 8 + TB - 1) / TB;
    const int gAg = (int)(((long long)NN * 32 + TB - 1) / TB);  // warp/node
    const int gGm = (NN + 127) / 128;                           // 782
    const int nScanBlk = (NN + SCAN_B - 1) / SCAN_B;            // 196

    // Order keeps the layer-1 GEMM at launch slot 4 (ncu capture window).
    cvtx_k<<<gCv, TB>>>(x);
    repack_k<<<48, 256>>>(Wm[0], Wm[1], Wm[2]);
    init_k<<<gN, TB>>>((const int*)ei, (const int*)batch);
    gemm_tc<<<gGm, TB>>>(0);                   // th = x @ W1
    prep_k<<<gE, TB>>>(ei, ew);
    scan1_k<<<nScanBlk, SCAN_B>>>();           // scan + dinv
    scan2_k<<<1, 256>>>(nScanBlk);
    scan3_k<<<nScanBlk, SCAN_B>>>();
    build_k<<<gE, TB>>>(ei, ew);

    // Layer 1 aggregation: ah = relu(b1 + dinv^2*th + gather(th))
    agg_k<<<gAg, TB>>>(v128[0]);

    // Layer 2
    gemm_tc<<<gGm, TB>>>(1);
    agg_k<<<gAg, TB>>>(v128[1]);

    // Layer 3
    gemm_tc<<<gGm, TB>>>(2);
    agg_k<<<gAg, TB>>>(v128[2]);

    // Two-stage pool + final linear
    pool1_k<<<GG * PCH, 128>>>(batch, lw);
    final_k<<<1, 64>>>(batch, linb, out);
}

// round 15
// speedup vs baseline: 1.2234x; 1.2234x over previous
#include <cuda_runtime.h>
#include <cuda_fp16.h>
#include <math.h>

// Problem constants (fixed by the reference)
#define NN 100000   // nodes
#define EE 1600000  // edges
#define HH 128      // channels
#define GG 64       // graphs
#define PCH 8       // pool chunks per graph

// ---------------- static device scratch (no allocations allowed) ----------
// fp16 activation ping-pong (fp32 math, fp16 storage), padded +128 rows so
// the GEMM needs no bounds checks (pad rows stay zero forever).
__device__ __align__(16) __half g_ah[(size_t)(NN + 128) * HH];
__device__ __align__(16) __half g_th[(size_t)(NN + 128) * HH];
// repacked W B-fragments, 3 layers, layout [layer][kc][nt][lane]
// (lane contiguous -> every B load is a coalesced 256B uint2 access)
__device__ __align__(16) uint2  g_bw[3 * 8 * 16 * 32];
__device__ float g_dinv[NN];              // deg -> d^{-1/2} (in place)
// CSR (destination-sorted) adjacency, built once
__device__ int   g_cnt[NN];               // int in-degree
__device__ int   g_off[NN + 1];           // exclusive scan of cnt
__device__ int   g_fill[NN];              // slot fill counters
__device__ int   g_bsum[256];             // block sums for scan
__device__ __align__(8) int2 g_adj[EE];   // {src, w-bits}, sorted by dst
__device__ float g_part[GG * PCH];        // pool partial dots
__device__ int   g_ei_is64;               // dtype flags (auto-detected)
__device__ int   g_b_is64;

// ---------------- x -> fp16 conversion (layer-1 GEMM input) ----------------
__global__ void cvtx_k(const float* __restrict__ x)
{
    int i = blockIdx.x * blockDim.x + threadIdx.x;   // over N*H/8 uint4
    if (i >= NN * HH / 8) return;
    const float4* p = (const float4*)x + 2 * (size_t)i;
    float4 u0 = p[0], u1 = p[1];
    union { __half2 h[4]; uint4 u; } cv;
    cv.h[0] = __float22half2_rn(make_float2(u0.x, u0.y));
    cv.h[1] = __float22half2_rn(make_float2(u0.z, u0.w));
    cv.h[2] = __float22half2_rn(make_float2(u1.x, u1.y));
    cv.h[3] = __float22half2_rn(make_float2(u1.z, u1.w));
    ((uint4*)g_ah)[i] = cv.u;
}

// ---------------- W -> B-fragment repack (all 3 layers at once) ------------
// B fragment for mma.m16n8k16.row.col (B = W[k][n], col-major 16x8 frag):
//   lane: b0=B[t2][g], b1=B[t2+1][g], b2=B[t2+8][g], b3=B[t2+9][g]
//   with t2=(lane%4)*2, g=lane/4;  reg0=(b0,b1), reg1=(b2,b3)
// Layout: g_bw[(((L*8)+kc)*16+nt)*32 + lane]  (lane contiguous)
__global__ void repack_k(const float* __restrict__ W0,
                         const float* __restrict__ W1,
                         const float* __restrict__ W2)
{
    int tid = blockIdx.x * blockDim.x + threadIdx.x;   // 0..12287
    if (tid >= 3 * 8 * 16 * 32) return;
    int lane = tid & 31;
    int nt   = (tid >> 5) & 15;
    int kc   = (tid >> 9) & 7;
    int L    = tid >> 12;
    const float* W = (L == 0) ? W0 : (L == 1) ? W1 : W2;
    int k0 = kc * 16 + (lane & 3) * 2;
    int n  = nt * 8 + (lane >> 2);
    float f0 = W[(k0 + 0) * 128 + n];
    float f1 = W[(k0 + 1) * 128 + n];
    float f2 = W[(k0 + 8) * 128 + n];
    float f3 = W[(k0 + 9) * 128 + n];
    union { __half2 h; unsigned u; } lo, hi;
    lo.h = __float22half2_rn(make_float2(f0, f1));
    hi.h = __float22half2_rn(make_float2(f2, f3));
    g_bw[tid] = make_uint2(lo.u, hi.u);
}

// ---------------- init + dtype detection (fused) ----------------------------
// int64 payloads with values < 2^31 have all odd 32-bit words zero; int32
// payloads essentially never do. Sampled offsets are in-bounds either way.
__global__ void init_k(const int* __restrict__ ei32,
                       const int* __restrict__ b32)
{
    int i = blockIdx.x * blockDim.x + threadIdx.x;
    if (i < NN) { g_dinv[i] = 1.0f; g_cnt[i] = 0; g_fill[i] = 0; }
    if (blockIdx.x == 0) {
        int tid = threadIdx.x;                   // 256 threads
        int je = 1 + 12500 * tid;                // odd words across [1, 2*EE)
        int ei_nz = (ei32[je] != 0);
        int jb = 50001 + 194 * tid;              // odd words, upper half of N
        int b_nz = (b32[jb] != 0);
        int any_ei = __syncthreads_or(ei_nz);
        int any_b  = __syncthreads_or(b_nz);
        if (tid == 0) {
            g_ei_is64 = (any_ei == 0);
            g_b_is64  = (any_b  == 0);
        }
    }
}

// ---------------- edge prep: weighted degree + int in-degree ---------------
__global__ void prep_k(const void* __restrict__ ei,
                       const float* __restrict__ ew) {
    int e = blockIdx.x * blockDim.x + threadIdx.x;
    if (e >= EE) return;
    int c;
    if (g_ei_is64) c = (int)((const long long*)ei)[EE + e];
    else           c = ((const int*)ei)[EE + e];
    atomicAdd(&g_dinv[c], ew[e]);           // weighted in-degree
    atomicAdd(&g_cnt[c], 1);                // integer in-degree (for CSR)
}

// ---------------- exclusive scan of g_cnt -> g_off (+ fused dinv) ----------
#define SCAN_B 512
__global__ void scan1_k() {      // per-block exclusive scan + block totals
    __shared__ int sm[SCAN_B];
    int t = threadIdx.x;
    int idx = blockIdx.x * SCAN_B + t;
    int v = (idx < NN) ? g_cnt[idx] : 0;
    sm[t] = v;
    if (idx < NN) {
        float d = g_dinv[idx];
        g_dinv[idx] = (d > 0.0f) ? rsqrtf(d) : 0.0f;
    }
    __syncthreads();
#pragma unroll
    for (int o = 1; o < SCAN_B; o <<= 1) {
        int x = (t >= o) ? sm[t - o] : 0;
        __syncthreads();
        sm[t] += x;
        __syncthreads();
    }
    if (idx < NN) g_off[idx] = sm[t] - v;        // exclusive
    if (t == SCAN_B - 1) g_bsum[blockIdx.x] = sm[t];
}
__global__ void scan2_k(int nblk) {  // single block: scan block totals
    __shared__ int sm[256];
    int t = threadIdx.x;
    int v = (t < nblk) ? g_bsum[t] : 0;
    sm[t] = v;
    __syncthreads();
#pragma unroll
    for (int o = 1; o < 256; o <<= 1) {
        int x = (t >= o) ? sm[t - o] : 0;
        __syncthreads();
        sm[t] += x;
        __syncthreads();
    }
    if (t < nblk) g_bsum[t] = sm[t] - v;         // exclusive
}
__global__ void scan3_k() {
    int idx = blockIdx.x * SCAN_B + threadIdx.x;
    if (idx < NN) g_off[idx] += g_bsum[blockIdx.x];
    if (idx == 0) g_off[NN] = EE;
}

// ---------------- build sorted adjacency (counting-sort fill) --------------
// decodes edge_index directly (no intermediate row/col arrays)
__global__ void build_k(const void* __restrict__ ei,
                        const float* __restrict__ ew) {
    int e = blockIdx.x * blockDim.x + threadIdx.x;
    if (e >= EE) return;
    int r, c;
    if (g_ei_is64) {
        const long long* p = (const long long*)ei;
        r = (int)p[e]; c = (int)p[EE + e];
    } else {
        const int* p = (const int*)ei;
        r = p[e]; c = p[EE + e];
    }
    int pos = g_off[c] + atomicAdd(&g_fill[c], 1);
    float w = g_dinv[r] * ew[e] * g_dinv[c];
    g_adj[pos] = make_int2(r, __float_as_int(w));
}

// ---------------- tensor-core GEMM: g_th = g_ah[N,128] @ W[128,128] --------
// mma.sync.m16n8k16 (fp16 in, fp32 accum). 256 threads = 8 warps:
// 4 m-warps x 2 n-warps; warp tile m32 x n64 (2 MMAs per B fragment);
// block tile 128x128, grid 782. B loads are coalesced uint2 (lane-major
// layout); per-layer B working set = 32KB -> L1-resident.
__global__ void __launch_bounds__(256, 2)
gemm_tc(int L)
{
    const int lane = threadIdx.x & 31;
    const int warp = threadIdx.x >> 5;
    const int wm = warp & 3;            // 0..3
    const int wn = warp >> 2;           // 0..1
    const int rowbase = blockIdx.x * 128 + wm * 32;

    const int g  = lane >> 2;           // 0..7
    const int t2 = (lane & 3) * 2;      // 0,2,4,6

    float c0[8][4], c1[8][4];           // two m16 frags x 8 n-tiles
#pragma unroll
    for (int nt = 0; nt < 8; ++nt)
#pragma unroll
        for (int j = 0; j < 4; ++j) { c0[nt][j] = 0.0f; c1[nt][j] = 0.0f; }

    const __half* pA0 = g_ah + (size_t)(rowbase + g)      * HH;
    const __half* pA1 = g_ah + (size_t)(rowbase + g + 8)  * HH;
    const __half* pA2 = g_ah + (size_t)(rowbase + g + 16) * HH;
    const __half* pA3 = g_ah + (size_t)(rowbase + g + 24) * HH;

    // B base for this lane/warp: [(L*8+kc)*16 + wn*8 + nt]*32 + lane
    const uint2* bbase = g_bw + ((size_t)(L * 8) * 16 + wn * 8) * 32 + lane;

#pragma unroll
    for (int kc = 0; kc < 8; ++kc) {
        int off = kc * 16 + t2;
        unsigned a00 = *(const unsigned*)(pA0 + off);
        unsigned a01 = *(const unsigned*)(pA1 + off);
        unsigned a02 = *(const unsigned*)(pA0 + off + 8);
        unsigned a03 = *(const unsigned*)(pA1 + off + 8);
        unsigned a10 = *(const unsigned*)(pA2 + off);
        unsigned a11 = *(const unsigned*)(pA3 + off);
        unsigned a12 = *(const unsigned*)(pA2 + off + 8);
        unsigned a13 = *(const unsigned*)(pA3 + off + 8);
        // 8 coalesced uint2 B loads (nt stride = 32 uint2, kc stride = 512)
        const uint2* bp = bbase + (size_t)kc * 16 * 32;
        uint2 b[8];
#pragma unroll
        for (int nt = 0; nt < 8; ++nt) b[nt] = __ldg(bp + (size_t)nt * 32);
#pragma unroll
        for (int nt = 0; nt < 8; ++nt) {
            asm volatile(
                "mma.sync.aligned.m16n8k16.row.col.f32.f16.f16.f32 "
                "{%0,%1,%2,%3}, {%4,%5,%6,%7}, {%8,%9}, {%0,%1,%2,%3};"
                : "+f"(c0[nt][0]), "+f"(c0[nt][1]),
                  "+f"(c0[nt][2]), "+f"(c0[nt][3])
                : "r"(a00), "r"(a01), "r"(a02), "r"(a03),
                  "r"(b[nt].x), "r"(b[nt].y));
            asm volatile(
                "mma.sync.aligned.m16n8k16.row.col.f32.f16.f16.f32 "
                "{%0,%1,%2,%3}, {%4,%5,%6,%7}, {%8,%9}, {%0,%1,%2,%3};"
                : "+f"(c1[nt][0]), "+f"(c1[nt][1]),
                  "+f"(c1[nt][2]), "+f"(c1[nt][3])
                : "r"(a10), "r"(a11), "r"(a12), "r"(a13),
                  "r"(b[nt].x), "r"(b[nt].y));
        }
    }

    // epilogue: fp16 stores (padded g_th -> no bounds checks)
    const size_t r0 = (size_t)(rowbase + g) * HH;
#pragma unroll
    for (int nt = 0; nt < 8; ++nt) {
        int colb = (wn * 8 + nt) * 8 + t2;
        union { __half2 h; unsigned u; } v;
        v.h = __float22half2_rn(make_float2(c0[nt][0], c0[nt][1]));
        *(unsigned*)(g_th + r0 + colb) = v.u;
        v.h = __float22half2_rn(make_float2(c0[nt][2], c0[nt][3]));
        *(unsigned*)(g_th + r0 + 8 * HH + colb) = v.u;
        v.h = __float22half2_rn(make_float2(c1[nt][0], c1[nt][1]));
        *(unsigned*)(g_th + r0 + 16 * HH + colb) = v.u;
        v.h = __float22half2_rn(make_float2(c1[nt][2], c1[nt][3]));
        *(unsigned*)(g_th + r0 + 24 * HH + colb) = v.u;
    }
}

// ---------------- fused aggregation (gather, no atomics) -------------------
// acc = bias + dinv[n]^2 * th[n] + sum_{e in in(n)} w[e] * th[src[e]]  (fp32)
// g_ah[n] = relu(acc) fp16. One warp per node; lane l owns channels [4l,4l+4).
__global__ void __launch_bounds__(256)
agg_k(const float* __restrict__ bias)
{
    int warp = (blockIdx.x * blockDim.x + threadIdx.x) >> 5;
    if (warp >= NN) return;
    int lane = threadIdx.x & 31;

    float d = g_dinv[warp];
    float s = d * d;
    float4 acc = ((const float4*)bias)[lane];
    {
        uint2 q = *((const uint2*)(g_th + (size_t)warp * HH) + lane);
        float2 f0 = __half22float2(*(const __half2*)&q.x);
        float2 f1 = __half22float2(*(const __half2*)&q.y);
        acc.x = fmaf(f0.x, s, acc.x); acc.y = fmaf(f0.y, s, acc.y);
        acc.z = fmaf(f1.x, s, acc.z); acc.w = fmaf(f1.y, s, acc.w);
    }

    int k   = g_off[warp];
    int end = g_off[warp + 1];

    for (; k + 16 <= end; k += 16) {
        int2 a[16]; uint2 q[16];
#pragma unroll
        for (int u = 0; u < 16; ++u) a[u] = __ldg(&g_adj[k + u]);
#pragma unroll
        for (int u = 0; u < 16; ++u)
            q[u] = __ldg((const uint2*)(g_th + (size_t)a[u].x * HH) + lane);
#pragma unroll
        for (int u = 0; u < 16; ++u) {
            float w = __int_as_float(a[u].y);
            float2 f0 = __half22float2(*(const __half2*)&q[u].x);
            float2 f1 = __half22float2(*(const __half2*)&q[u].y);
            acc.x = fmaf(f0.x, w, acc.x);
            acc.y = fmaf(f0.y, w, acc.y);
            acc.z = fmaf(f1.x, w, acc.z);
            acc.w = fmaf(f1.y, w, acc.w);
        }
    }
    for (; k + 4 <= end; k += 4) {
        int2 a[4]; uint2 q[4];
#pragma unroll
        for (int u = 0; u < 4; ++u) a[u] = __ldg(&g_adj[k + u]);
#pragma unroll
        for (int u = 0; u < 4; ++u)
            q[u] = __ldg((const uint2*)(g_th + (size_t)a[u].x * HH) + lane);
#pragma unroll
        for (int u = 0; u < 4; ++u) {
            float w = __int_as_float(a[u].y);
            float2 f0 = __half22float2(*(const __half2*)&q[u].x);
            float2 f1 = __half22float2(*(const __half2*)&q[u].y);
            acc.x = fmaf(f0.x, w, acc.x);
            acc.y = fmaf(f0.y, w, acc.y);
            acc.z = fmaf(f1.x, w, acc.z);
            acc.w = fmaf(f1.y, w, acc.w);
        }
    }
    for (; k < end; ++k) {
        int2 a = __ldg(&g_adj[k]);
        float w = __int_as_float(a.y);
        uint2 q = __ldg((const uint2*)(g_th + (size_t)a.x * HH) + lane);
        float2 f0 = __half22float2(*(const __half2*)&q.x);
        float2 f1 = __half22float2(*(const __half2*)&q.y);
        acc.x = fmaf(f0.x, w, acc.x); acc.y = fmaf(f0.y, w, acc.y);
        acc.z = fmaf(f1.x, w, acc.z); acc.w = fmaf(f1.y, w, acc.w);
    }

    acc.x = fmaxf(acc.x, 0.0f); acc.y = fmaxf(acc.y, 0.0f);
    acc.z = fmaxf(acc.z, 0.0f); acc.w = fmaxf(acc.w, 0.0f);
    union { __half2 h[2]; uint2 u; } cv;
    cv.h[0] = __float22half2_rn(make_float2(acc.x, acc.y));
    cv.h[1] = __float22half2_rn(make_float2(acc.z, acc.w));
    *((uint2*)(g_ah + (size_t)warp * HH) + lane) = cv.u;
}

// ---------------- two-stage pool + final linear (atomic-free) --------------
__device__ __forceinline__ int lower_bound_batch(const void* batch, int tgt)
{
    int lo = 0, hi = NN;
    while (lo < hi) {
        int mid = (lo + hi) >> 1;
        long long v = g_b_is64 ? ((const long long*)batch)[mid]
                               : (long long)((const int*)batch)[mid];
        if (v < tgt) lo = mid + 1; else hi = mid;
    }
    return lo;
}

// stage 1: 512 blocks = 64 graphs x 8 chunks; partial dot of channel sums
// with lin_w over a row sub-range (linear, so chunk partials sum exactly).
__global__ void pool1_k(const void* __restrict__ batch,
                        const float* __restrict__ lw)
{
    int g  = blockIdx.x >> 3;        // graph
    int ch = blockIdx.x & 7;         // chunk
    int t  = threadIdx.x;            // 128 threads = channel
    __shared__ int se[2];
    if (t == 0) se[0] = lower_bound_batch(batch, g);
    if (t == 1) se[1] = lower_bound_batch(batch, g + 1);
    __syncthreads();
    int s = se[0], len = se[1] - se[0];
    int c0 = s + (int)(((long long)len * ch) >> 3);
    int c1 = s + (int)(((long long)len * (ch + 1)) >> 3);

    float sum = 0.0f;
    int r = c0;
    for (; r + 4 <= c1; r += 4) {
        sum += __half2float(g_ah[(size_t)(r + 0) * HH + t]);
        sum += __half2float(g_ah[(size_t)(r + 1) * HH + t]);
        sum += __half2float(g_ah[(size_t)(r + 2) * HH + t]);
        sum += __half2float(g_ah[(size_t)(r + 3) * HH + t]);
    }
    for (; r < c1; ++r)
        sum += __half2float(g_ah[(size_t)r * HH + t]);

    float v = sum * lw[t];
#pragma unroll
    for (int o = 16; o > 0; o >>= 1)
        v += __shfl_down_sync(0xffffffffu, v, o);
    __shared__ float sm[4];
    if ((t & 31) == 0) sm[t >> 5] = v;
    __syncthreads();
    if (t == 0) g_part[blockIdx.x] = sm[0] + sm[1] + sm[2] + sm[3];
}

// stage 2: combine chunk partials, divide by node count, add bias.
__global__ void final_k(const void* __restrict__ batch,
                        const float* __restrict__ lb,
                        float* __restrict__ out)
{
    int g = threadIdx.x;             // 64 threads
    if (g >= GG) return;
    int s = lower_bound_batch(batch, g);
    int e = lower_bound_batch(batch, g + 1);
    float sum = 0.0f;
#pragma unroll
    for (int c = 0; c < PCH; ++c) sum += g_part[g * PCH + c];
    out[g] = sum / fmaxf((float)(e - s), 1.0f) + lb[0];
}

// ---------------- launcher --------------------------------------------------
extern "C" void kernel_launch(void* const* d_in, const int* in_sizes, int n_in,
                              void* d_out, int out_size)
{
    // Locate inputs by element count (robust to metadata ordering).
    const float* x = nullptr;
    const float* ew = nullptr;
    const void*  ei = nullptr;     // int32 or int64 (auto-detected on device)
    const void*  batch = nullptr;  // int32 or int64
    const float* Wm[3] = {nullptr, nullptr, nullptr};
    const float* v128[4] = {nullptr, nullptr, nullptr, nullptr}; // b1,b2,b3,lin_w
    const float* linb = nullptr;
    int wi = 0, bi = 0;
    for (int i = 0; i < n_in; ++i) {
        int s = in_sizes[i];
        if      (s == NN * HH)  x = (const float*)d_in[i];
        else if (s == EE)       ew = (const float*)d_in[i];
        else if (s == 2 * EE)   ei = d_in[i];
        else if (s == NN)       batch = d_in[i];
        else if (s == HH * HH)  { if (wi < 3) Wm[wi++] = (const float*)d_in[i]; }
        else if (s == HH)       { if (bi < 4) v128[bi++] = (const float*)d_in[i]; }
        else if (s == 1)        linb = (const float*)d_in[i];
    }
    const float* lw = v128[3];
    float* out = (float*)d_out;

    const int TB = 256;
    const int gN  = (NN + TB - 1) / TB;
    const int gE  = (EE + TB - 1) / TB;
    const int gCv = (NN * HH / 8 + TB - 1) / TB;
    const int gAg = (int)(((long long)NN * 32 + TB - 1) / TB);  // warp/node
    const int gGm = (NN + 127) / 128;                           // 782
    const int nScanBlk = (NN + SCAN_B - 1) / SCAN_B;            // 196

    // Order keeps the layer-1 GEMM at launch slot 4 (ncu capture window).
    cvtx_k<<<gCv, TB>>>(x);
    repack_k<<<48, 256>>>(Wm[0], Wm[1], Wm[2]);
    init_k<<<gN, TB>>>((const int*)ei, (const int*)batch);
    gemm_tc<<<gGm, TB>>>(0);                   // th = x @ W1
    prep_k<<<gE, TB>>>(ei, ew);
    scan1_k<<<nScanBlk, SCAN_B>>>();           // scan + dinv
    scan2_k<<<1, 256>>>(nScanBlk);
    scan3_k<<<nScanBlk, SCAN_B>>>();
    build_k<<<gE, TB>>>(ei, ew);

    // Layer 1 aggregation: ah = relu(b1 + dinv^2*th + gather(th))
    agg_k<<<gAg, TB>>>(v128[0]);

    // Layer 2
    gemm_tc<<<gGm, TB>>>(1);
    agg_k<<<gAg, TB>>>(v128[1]);

    // Layer 3
    gemm_tc<<<gGm, TB>>>(2);
    agg_k<<<gAg, TB>>>(v128[2]);

    // Two-stage pool + final linear
    pool1_k<<<GG * PCH, 128>>>(batch, lw);
    final_k<<<1, 64>>>(batch, linb, out);
}

// round 16
// speedup vs baseline: 1.2987x; 1.0616x over previous
#include <cuda_runtime.h>
#include <cuda_fp16.h>
#include <math.h>

// Problem constants (fixed by the reference)
#define NN 100000   // nodes
#define EE 1600000  // edges
#define HH 128      // channels
#define GG 64       // graphs
#define PCH 8       // pool chunks per graph

// ---------------- static device scratch (no allocations allowed) ----------
// fp16 activation ping-pong (fp32 math, fp16 storage), padded +128 rows so
// the GEMM needs no bounds checks (pad rows stay zero forever).
__device__ __align__(16) __half g_ah[(size_t)(NN + 128) * HH];
__device__ __align__(16) __half g_th[(size_t)(NN + 128) * HH];
// repacked W B-fragments, 3 layers, layout [layer][kc][nt][lane]
// (lane contiguous -> every B load is a coalesced 256B uint2 access)
__device__ __align__(16) uint2  g_bw[3 * 8 * 16 * 32];
__device__ float g_dinv[NN];              // deg -> d^{-1/2} (in place)
// CSR (destination-sorted) adjacency, built once
__device__ int   g_cnt[NN];               // int in-degree
__device__ int   g_off[NN + 1];           // exclusive scan of cnt
__device__ int   g_fill[NN];              // slot fill counters
__device__ int   g_bsum[256];             // block sums for scan
__device__ __align__(8) int2 g_adj[EE];   // {src, w-bits}, sorted by dst
__device__ float g_part[GG * PCH];        // pool partial dots
__device__ int   g_ei_is64;               // dtype flags (auto-detected)
__device__ int   g_b_is64;

// ---------------- x -> fp16 conversion (layer-1 GEMM input) ----------------
__global__ void cvtx_k(const float* __restrict__ x)
{
    int i = blockIdx.x * blockDim.x + threadIdx.x;   // over N*H/8 uint4
    if (i >= NN * HH / 8) return;
    const float4* p = (const float4*)x + 2 * (size_t)i;
    float4 u0 = p[0], u1 = p[1];
    union { __half2 h[4]; uint4 u; } cv;
    cv.h[0] = __float22half2_rn(make_float2(u0.x, u0.y));
    cv.h[1] = __float22half2_rn(make_float2(u0.z, u0.w));
    cv.h[2] = __float22half2_rn(make_float2(u1.x, u1.y));
    cv.h[3] = __float22half2_rn(make_float2(u1.z, u1.w));
    ((uint4*)g_ah)[i] = cv.u;
}

// ---------------- W -> B-fragment repack (all 3 layers at once) ------------
// B fragment for mma.m16n8k16.row.col (B = W[k][n], col-major 16x8 frag):
//   lane: b0=B[t2][g], b1=B[t2+1][g], b2=B[t2+8][g], b3=B[t2+9][g]
//   with t2=(lane%4)*2, g=lane/4;  reg0=(b0,b1), reg1=(b2,b3)
// Layout: g_bw[(((L*8)+kc)*16+nt)*32 + lane]  (lane contiguous)
__global__ void repack_k(const float* __restrict__ W0,
                         const float* __restrict__ W1,
                         const float* __restrict__ W2)
{
    int tid = blockIdx.x * blockDim.x + threadIdx.x;   // 0..12287
    if (tid >= 3 * 8 * 16 * 32) return;
    int lane = tid & 31;
    int nt   = (tid >> 5) & 15;
    int kc   = (tid >> 9) & 7;
    int L    = tid >> 12;
    const float* W = (L == 0) ? W0 : (L == 1) ? W1 : W2;
    int k0 = kc * 16 + (lane & 3) * 2;
    int n  = nt * 8 + (lane >> 2);
    float f0 = W[(k0 + 0) * 128 + n];
    float f1 = W[(k0 + 1) * 128 + n];
    float f2 = W[(k0 + 8) * 128 + n];
    float f3 = W[(k0 + 9) * 128 + n];
    union { __half2 h; unsigned u; } lo, hi;
    lo.h = __float22half2_rn(make_float2(f0, f1));
    hi.h = __float22half2_rn(make_float2(f2, f3));
    g_bw[tid] = make_uint2(lo.u, hi.u);
}

// ---------------- init + dtype detection (fused) ----------------------------
// int64 payloads with values < 2^31 have all odd 32-bit words zero; int32
// payloads essentially never do. Sampled offsets are in-bounds either way.
__global__ void init_k(const int* __restrict__ ei32,
                       const int* __restrict__ b32)
{
    int i = blockIdx.x * blockDim.x + threadIdx.x;
    if (i < NN) { g_dinv[i] = 1.0f; g_cnt[i] = 0; g_fill[i] = 0; }
    if (blockIdx.x == 0) {
        int tid = threadIdx.x;                   // 256 threads
        int je = 1 + 12500 * tid;                // odd words across [1, 2*EE)
        int ei_nz = (ei32[je] != 0);
        int jb = 50001 + 194 * tid;              // odd words, upper half of N
        int b_nz = (b32[jb] != 0);
        int any_ei = __syncthreads_or(ei_nz);
        int any_b  = __syncthreads_or(b_nz);
        if (tid == 0) {
            g_ei_is64 = (any_ei == 0);
            g_b_is64  = (any_b  == 0);
        }
    }
}

// ---------------- edge prep: weighted degree + int in-degree ---------------
__global__ void prep_k(const void* __restrict__ ei,
                       const float* __restrict__ ew) {
    int e = blockIdx.x * blockDim.x + threadIdx.x;
    if (e >= EE) return;
    int c;
    if (g_ei_is64) c = (int)((const long long*)ei)[EE + e];
    else           c = ((const int*)ei)[EE + e];
    atomicAdd(&g_dinv[c], ew[e]);           // weighted in-degree
    atomicAdd(&g_cnt[c], 1);                // integer in-degree (for CSR)
}

// ---------------- exclusive scan of g_cnt -> g_off (+ fused dinv) ----------
#define SCAN_B 512
__global__ void scan1_k() {      // per-block exclusive scan + block totals
    __shared__ int sm[SCAN_B];
    int t = threadIdx.x;
    int idx = blockIdx.x * SCAN_B + t;
    int v = (idx < NN) ? g_cnt[idx] : 0;
    sm[t] = v;
    if (idx < NN) {
        float d = g_dinv[idx];
        g_dinv[idx] = (d > 0.0f) ? rsqrtf(d) : 0.0f;
    }
    __syncthreads();
#pragma unroll
    for (int o = 1; o < SCAN_B; o <<= 1) {
        int x = (t >= o) ? sm[t - o] : 0;
        __syncthreads();
        sm[t] += x;
        __syncthreads();
    }
    if (idx < NN) g_off[idx] = sm[t] - v;        // exclusive
    if (t == SCAN_B - 1) g_bsum[blockIdx.x] = sm[t];
}
__global__ void scan2_k(int nblk) {  // single block: scan block totals
    __shared__ int sm[256];
    int t = threadIdx.x;
    int v = (t < nblk) ? g_bsum[t] : 0;
    sm[t] = v;
    __syncthreads();
#pragma unroll
    for (int o = 1; o < 256; o <<= 1) {
        int x = (t >= o) ? sm[t - o] : 0;
        __syncthreads();
        sm[t] += x;
        __syncthreads();
    }
    if (t < nblk) g_bsum[t] = sm[t] - v;         // exclusive
}
__global__ void scan3_k() {
    int idx = blockIdx.x * SCAN_B + threadIdx.x;
    if (idx < NN) g_off[idx] += g_bsum[blockIdx.x];
    if (idx == 0) g_off[NN] = EE;
}

// ---------------- build sorted adjacency (counting-sort fill) --------------
// decodes edge_index directly (no intermediate row/col arrays)
__global__ void build_k(const void* __restrict__ ei,
                        const float* __restrict__ ew) {
    int e = blockIdx.x * blockDim.x + threadIdx.x;
    if (e >= EE) return;
    int r, c;
    if (g_ei_is64) {
        const long long* p = (const long long*)ei;
        r = (int)p[e]; c = (int)p[EE + e];
    } else {
        const int* p = (const int*)ei;
        r = p[e]; c = p[EE + e];
    }
    int pos = g_off[c] + atomicAdd(&g_fill[c], 1);
    float w = g_dinv[r] * ew[e] * g_dinv[c];
    g_adj[pos] = make_int2(r, __float_as_int(w));
}

// ---------------- tensor-core GEMM: g_th = g_ah[N,128] @ W[128,128] --------
// mma.sync.m16n8k16 (fp16 in, fp32 accum). 256 threads = 8 warps:
// 4 m-warps x 2 n-warps; warp tile m32 x n64. The 128x128 A tile is staged
// once in smem (coalesced uint4, row pitch 136 halfs -> conflict-free LDSM)
// and consumed via ldmatrix.x4 (2 LDSM per warp per kc instead of 8
// scattered 4B LDGs). B loads stay coalesced uint2 and L1-resident.
__global__ void __launch_bounds__(256, 2)
gemm_tc(int L)
{
    __shared__ __align__(16) __half As[128][136];   // 34.8 KB, pad=8 halfs

    const int tid  = threadIdx.x;
    const int lane = tid & 31;
    const int warp = tid >> 5;
    const int wm = warp & 3;            // 0..3
    const int wn = warp >> 2;           // 0..1
    const int blockrow = blockIdx.x * 128;

    // stage A tile: 128 rows x 16 uint4, fully coalesced
#pragma unroll
    for (int i = tid; i < 128 * 16; i += 256) {
        int row = i >> 4, c16 = i & 15;
        uint4 v = *(const uint4*)(g_ah + (size_t)(blockrow + row) * HH
                                  + c16 * 8);
        *(uint4*)&As[row][c16 * 8] = v;
    }
    __syncthreads();

    const int g  = lane >> 2;           // 0..7
    const int t2 = (lane & 3) * 2;      // 0,2,4,6

    float c0[8][4], c1[8][4];           // two m16 frags x 8 n-tiles
#pragma unroll
    for (int nt = 0; nt < 8; ++nt)
#pragma unroll
        for (int j = 0; j < 4; ++j) { c0[nt][j] = 0.0f; c1[nt][j] = 0.0f; }

    // ldmatrix.x4 lane addressing for an m16k16 A fragment:
    //   lanes 0-15  -> rows 0..15  at col kc*16
    //   lanes 16-31 -> rows 0..15  at col kc*16+8
    const int arow = wm * 32 + (lane & 15);
    const int acol = (lane >> 4) * 8;
    unsigned aaddr0 = (unsigned)__cvta_generic_to_shared(&As[arow][acol]);
    unsigned aaddr1 = (unsigned)__cvta_generic_to_shared(&As[arow + 16][acol]);

    // B base for this lane/warp: [(L*8+kc)*16 + wn*8 + nt]*32 + lane
    const uint2* bbase = g_bw + ((size_t)(L * 8) * 16 + wn * 8) * 32 + lane;

#pragma unroll
    for (int kc = 0; kc < 8; ++kc) {
        unsigned a00, a01, a02, a03, a10, a11, a12, a13;
        asm volatile(
            "ldmatrix.sync.aligned.m8n8.x4.shared.b16 {%0,%1,%2,%3}, [%4];"
            : "=r"(a00), "=r"(a01), "=r"(a02), "=r"(a03)
            : "r"(aaddr0 + kc * 32));
        asm volatile(
            "ldmatrix.sync.aligned.m8n8.x4.shared.b16 {%0,%1,%2,%3}, [%4];"
            : "=r"(a10), "=r"(a11), "=r"(a12), "=r"(a13)
            : "r"(aaddr1 + kc * 32));
        // 8 coalesced uint2 B loads (nt stride = 32 uint2, kc stride = 512)
        const uint2* bp = bbase + (size_t)kc * 16 * 32;
        uint2 b[8];
#pragma unroll
        for (int nt = 0; nt < 8; ++nt) b[nt] = __ldg(bp + (size_t)nt * 32);
#pragma unroll
        for (int nt = 0; nt < 8; ++nt) {
            asm volatile(
                "mma.sync.aligned.m16n8k16.row.col.f32.f16.f16.f32 "
                "{%0,%1,%2,%3}, {%4,%5,%6,%7}, {%8,%9}, {%0,%1,%2,%3};"
                : "+f"(c0[nt][0]), "+f"(c0[nt][1]),
                  "+f"(c0[nt][2]), "+f"(c0[nt][3])
                : "r"(a00), "r"(a01), "r"(a02), "r"(a03),
                  "r"(b[nt].x), "r"(b[nt].y));
            asm volatile(
                "mma.sync.aligned.m16n8k16.row.col.f32.f16.f16.f32 "
                "{%0,%1,%2,%3}, {%4,%5,%6,%7}, {%8,%9}, {%0,%1,%2,%3};"
                : "+f"(c1[nt][0]), "+f"(c1[nt][1]),
                  "+f"(c1[nt][2]), "+f"(c1[nt][3])
                : "r"(a10), "r"(a11), "r"(a12), "r"(a13),
                  "r"(b[nt].x), "r"(b[nt].y));
        }
    }

    // epilogue: fp16 stores (padded g_th -> no bounds checks)
    const size_t r0 = (size_t)(blockrow + wm * 32 + g) * HH;
#pragma unroll
    for (int nt = 0; nt < 8; ++nt) {
        int colb = (wn * 8 + nt) * 8 + t2;
        union { __half2 h; unsigned u; } v;
        v.h = __float22half2_rn(make_float2(c0[nt][0], c0[nt][1]));
        *(unsigned*)(g_th + r0 + colb) = v.u;
        v.h = __float22half2_rn(make_float2(c0[nt][2], c0[nt][3]));
        *(unsigned*)(g_th + r0 + 8 * HH + colb) = v.u;
        v.h = __float22half2_rn(make_float2(c1[nt][0], c1[nt][1]));
        *(unsigned*)(g_th + r0 + 16 * HH + colb) = v.u;
        v.h = __float22half2_rn(make_float2(c1[nt][2], c1[nt][3]));
        *(unsigned*)(g_th + r0 + 24 * HH + colb) = v.u;
    }
}

// ---------------- fused aggregation (gather, no atomics) -------------------
// acc = bias + dinv[n]^2 * th[n] + sum_{e in in(n)} w[e] * th[src[e]]  (fp32)
// g_ah[n] = relu(acc) fp16. One warp per node; lane l owns channels [4l,4l+4).
__global__ void __launch_bounds__(256)
agg_k(const float* __restrict__ bias)
{
    int warp = (blockIdx.x * blockDim.x + threadIdx.x) >> 5;
    if (warp >= NN) return;
    int lane = threadIdx.x & 31;

    float d = g_dinv[warp];
    float s = d * d;
    float4 acc = ((const float4*)bias)[lane];
    {
        uint2 q = *((const uint2*)(g_th + (size_t)warp * HH) + lane);
        float2 f0 = __half22float2(*(const __half2*)&q.x);
        float2 f1 = __half22float2(*(const __half2*)&q.y);
        acc.x = fmaf(f0.x, s, acc.x); acc.y = fmaf(f0.y, s, acc.y);
        acc.z = fmaf(f1.x, s, acc.z); acc.w = fmaf(f1.y, s, acc.w);
    }

    int k   = g_off[warp];
    int end = g_off[warp + 1];

    for (; k + 16 <= end; k += 16) {
        int2 a[16]; uint2 q[16];
#pragma unroll
        for (int u = 0; u < 16; ++u) a[u] = __ldg(&g_adj[k + u]);
#pragma unroll
        for (int u = 0; u < 16; ++u)
            q[u] = __ldg((const uint2*)(g_th + (size_t)a[u].x * HH) + lane);
#pragma unroll
        for (int u = 0; u < 16; ++u) {
            float w = __int_as_float(a[u].y);
            float2 f0 = __half22float2(*(const __half2*)&q[u].x);
            float2 f1 = __half22float2(*(const __half2*)&q[u].y);
            acc.x = fmaf(f0.x, w, acc.x);
            acc.y = fmaf(f0.y, w, acc.y);
            acc.z = fmaf(f1.x, w, acc.z);
            acc.w = fmaf(f1.y, w, acc.w);
        }
    }
    for (; k + 4 <= end; k += 4) {
        int2 a[4]; uint2 q[4];
#pragma unroll
        for (int u = 0; u < 4; ++u) a[u] = __ldg(&g_adj[k + u]);
#pragma unroll
        for (int u = 0; u < 4; ++u)
            q[u] = __ldg((const uint2*)(g_th + (size_t)a[u].x * HH) + lane);
#pragma unroll
        for (int u = 0; u < 4; ++u) {
            float w = __int_as_float(a[u].y);
            float2 f0 = __half22float2(*(const __half2*)&q[u].x);
            float2 f1 = __half22float2(*(const __half2*)&q[u].y);
            acc.x = fmaf(f0.x, w, acc.x);
            acc.y = fmaf(f0.y, w, acc.y);
            acc.z = fmaf(f1.x, w, acc.z);
            acc.w = fmaf(f1.y, w, acc.w);
        }
    }
    for (; k < end; ++k) {
        int2 a = __ldg(&g_adj[k]);
        float w = __int_as_float(a.y);
        uint2 q = __ldg((const uint2*)(g_th + (size_t)a.x * HH) + lane);
        float2 f0 = __half22float2(*(const __half2*)&q.x);
        float2 f1 = __half22float2(*(const __half2*)&q.y);
        acc.x = fmaf(f0.x, w, acc.x); acc.y = fmaf(f0.y, w, acc.y);
        acc.z = fmaf(f1.x, w, acc.z); acc.w = fmaf(f1.y, w, acc.w);
    }

    acc.x = fmaxf(acc.x, 0.0f); acc.y = fmaxf(acc.y, 0.0f);
    acc.z = fmaxf(acc.z, 0.0f); acc.w = fmaxf(acc.w, 0.0f);
    union { __half2 h[2]; uint2 u; } cv;
    cv.h[0] = __float22half2_rn(make_float2(acc.x, acc.y));
    cv.h[1] = __float22half2_rn(make_float2(acc.z, acc.w));
    *((uint2*)(g_ah + (size_t)warp * HH) + lane) = cv.u;
}

// ---------------- two-stage pool + final linear (atomic-free) --------------
__device__ __forceinline__ int lower_bound_batch(const void* batch, int tgt)
{
    int lo = 0, hi = NN;
    while (lo < hi) {
        int mid = (lo + hi) >> 1;
        long long v = g_b_is64 ? ((const long long*)batch)[mid]
                               : (long long)((const int*)batch)[mid];
        if (v < tgt) lo = mid + 1; else hi = mid;
    }
    return lo;
}

// stage 1: 512 blocks = 64 graphs x 8 chunks; partial dot of channel sums
// with lin_w over a row sub-range (linear, so chunk partials sum exactly).
__global__ void pool1_k(const void* __restrict__ batch,
                        const float* __restrict__ lw)
{
    int g  = blockIdx.x >> 3;        // graph
    int ch = blockIdx.x & 7;         // chunk
    int t  = threadIdx.x;            // 128 threads = channel
    __shared__ int se[2];
    if (t == 0) se[0] = lower_bound_batch(batch, g);
    if (t == 1) se[1] = lower_bound_batch(batch, g + 1);
    __syncthreads();
    int s = se[0], len = se[1] - se[0];
    int c0 = s + (int)(((long long)len * ch) >> 3);
    int c1 = s + (int)(((long long)len * (ch + 1)) >> 3);

    float sum = 0.0f;
    int r = c0;
    for (; r + 4 <= c1; r += 4) {
        sum += __half2float(g_ah[(size_t)(r + 0) * HH + t]);
        sum += __half2float(g_ah[(size_t)(r + 1) * HH + t]);
        sum += __half2float(g_ah[(size_t)(r + 2) * HH + t]);
        sum += __half2float(g_ah[(size_t)(r + 3) * HH + t]);
    }
    for (; r < c1; ++r)
        sum += __half2float(g_ah[(size_t)r * HH + t]);

    float v = sum * lw[t];
#pragma unroll
    for (int o = 16; o > 0; o >>= 1)
        v += __shfl_down_sync(0xffffffffu, v, o);
    __shared__ float sm[4];
    if ((t & 31) == 0) sm[t >> 5] = v;
    __syncthreads();
    if (t == 0) g_part[blockIdx.x] = sm[0] + sm[1] + sm[2] + sm[3];
}

// stage 2: combine chunk partials, divide by node count, add bias.
__global__ void final_k(const void* __restrict__ batch,
                        const float* __restrict__ lb,
                        float* __restrict__ out)
{
    int g = threadIdx.x;             // 64 threads
    if (g >= GG) return;
    int s = lower_bound_batch(batch, g);
    int e = lower_bound_batch(batch, g + 1);
    float sum = 0.0f;
#pragma unroll
    for (int c = 0; c < PCH; ++c) sum += g_part[g * PCH + c];
    out[g] = sum / fmaxf((float)(e - s), 1.0f) + lb[0];
}

// ---------------- launcher --------------------------------------------------
extern "C" void kernel_launch(void* const* d_in, const int* in_sizes, int n_in,
                              void* d_out, int out_size)
{
    // Locate inputs by element count (robust to metadata ordering).
    const float* x = nullptr;
    const float* ew = nullptr;
    const void*  ei = nullptr;     // int32 or int64 (auto-detected on device)
    const void*  batch = nullptr;  // int32 or int64
    const float* Wm[3] = {nullptr, nullptr, nullptr};
    const float* v128[4] = {nullptr, nullptr, nullptr, nullptr}; // b1,b2,b3,lin_w
    const float* linb = nullptr;
    int wi = 0, bi = 0;
    for (int i = 0; i < n_in; ++i) {
        int s = in_sizes[i];
        if      (s == NN * HH)  x = (const float*)d_in[i];
        else if (s == EE)       ew = (const float*)d_in[i];
        else if (s == 2 * EE)   ei = d_in[i];
        else if (s == NN)       batch = d_in[i];
        else if (s == HH * HH)  { if (wi < 3) Wm[wi++] = (const float*)d_in[i]; }
        else if (s == HH)       { if (bi < 4) v128[bi++] = (const float*)d_in[i]; }
        else if (s == 1)        linb = (const float*)d_in[i];
    }
    const float* lw = v128[3];
    float* out = (float*)d_out;

    const int TB = 256;
    const int gN  = (NN + TB - 1) / TB;
    const int gE  = (EE + TB - 1) / TB;
    const int gCv = (NN * HH / 8 + TB - 1) / TB;
    const int gAg = (int)(((long long)NN * 32 + TB - 1) / TB);  // warp/node
    const int gGm = (NN + 127) / 128;                           // 782
    const int nScanBlk = (NN + SCAN_B - 1) / SCAN_B;            // 196

    // Order keeps the layer-1 GEMM at launch slot 4 (ncu capture window).
    cvtx_k<<<gCv, TB>>>(x);
    repack_k<<<48, 256>>>(Wm[0], Wm[1], Wm[2]);
    init_k<<<gN, TB>>>((const int*)ei, (const int*)batch);
    gemm_tc<<<gGm, TB>>>(0);                   // th = x @ W1
    prep_k<<<gE, TB>>>(ei, ew);
    scan1_k<<<nScanBlk, SCAN_B>>>();           // scan + dinv
    scan2_k<<<1, 256>>>(nScanBlk);
    scan3_k<<<nScanBlk, SCAN_B>>>();
    build_k<<<gE, TB>>>(ei, ew);

    // Layer 1 aggregation: ah = relu(b1 + dinv^2*th + gather(th))
    agg_k<<<gAg, TB>>>(v128[0]);

    // Layer 2
    gemm_tc<<<gGm, TB>>>(1);
    agg_k<<<gAg, TB>>>(v128[1]);

    // Layer 3
    gemm_tc<<<gGm, TB>>>(2);
    agg_k<<<gAg, TB>>>(v128[2]);

    // Two-stage pool + final linear
    pool1_k<<<GG * PCH, 128>>>(batch, lw);
    final_k<<<1, 64>>>(batch, linb, out);
}

// round 17
// speedup vs baseline: 1.3248x; 1.0201x over previous
#include <cuda_runtime.h>
#include <cuda_fp16.h>
#include <math.h>

// Problem constants (fixed by the reference)
#define NN 100000   // nodes
#define EE 1600000  // edges
#define HH 128      // channels
#define GG 64       // graphs
#define PCH 8       // pool chunks per graph

// ---------------- static device scratch (no allocations allowed) ----------
// fp16 activation ping-pong (fp32 math, fp16 storage), padded +128 rows so
// the GEMM needs no bounds checks (pad rows stay zero forever).
__device__ __align__(16) __half g_ah[(size_t)(NN + 128) * HH];
__device__ __align__(16) __half g_th[(size_t)(NN + 128) * HH];
// repacked W B-fragments, 3 layers, layout [layer][kc][nt][lane]
// (lane contiguous -> every B load is a coalesced 256B uint2 access)
__device__ __align__(16) uint2  g_bw[3 * 8 * 16 * 32];
__device__ float g_dinv[NN];              // deg -> d^{-1/2} (in place)
// CSR (destination-sorted) adjacency, built once
__device__ int   g_cnt[NN];               // int in-degree
__device__ int   g_off[NN + 1];           // exclusive scan of cnt
__device__ int   g_fill[NN];              // slot fill counters
__device__ int   g_bsum[256];             // block sums for scan
__device__ __align__(8) int2 g_adj[EE];   // {src, w-bits}, sorted by dst
__device__ float g_part[GG * PCH];        // pool partial dots
__device__ int   g_ei_is64;               // dtype flags (auto-detected)
__device__ int   g_b_is64;

// ---------------- x -> fp16 conversion (layer-1 GEMM input) ----------------
__global__ void cvtx_k(const float* __restrict__ x)
{
    int i = blockIdx.x * blockDim.x + threadIdx.x;   // over N*H/8 uint4
    if (i >= NN * HH / 8) return;
    const float4* p = (const float4*)x + 2 * (size_t)i;
    float4 u0 = p[0], u1 = p[1];
    union { __half2 h[4]; uint4 u; } cv;
    cv.h[0] = __float22half2_rn(make_float2(u0.x, u0.y));
    cv.h[1] = __float22half2_rn(make_float2(u0.z, u0.w));
    cv.h[2] = __float22half2_rn(make_float2(u1.x, u1.y));
    cv.h[3] = __float22half2_rn(make_float2(u1.z, u1.w));
    ((uint4*)g_ah)[i] = cv.u;
}

// ---------------- W -> B-fragment repack (all 3 layers at once) ------------
// B fragment for mma.m16n8k16.row.col (B = W[k][n], col-major 16x8 frag):
//   lane: b0=B[t2][g], b1=B[t2+1][g], b2=B[t2+8][g], b3=B[t2+9][g]
//   with t2=(lane%4)*2, g=lane/4;  reg0=(b0,b1), reg1=(b2,b3)
// Layout: g_bw[(((L*8)+kc)*16+nt)*32 + lane]  (lane contiguous)
__global__ void repack_k(const float* __restrict__ W0,
                         const float* __restrict__ W1,
                         const float* __restrict__ W2)
{
    int tid = blockIdx.x * blockDim.x + threadIdx.x;   // 0..12287
    if (tid >= 3 * 8 * 16 * 32) return;
    int lane = tid & 31;
    int nt   = (tid >> 5) & 15;
    int kc   = (tid >> 9) & 7;
    int L    = tid >> 12;
    const float* W = (L == 0) ? W0 : (L == 1) ? W1 : W2;
    int k0 = kc * 16 + (lane & 3) * 2;
    int n  = nt * 8 + (lane >> 2);
    float f0 = W[(k0 + 0) * 128 + n];
    float f1 = W[(k0 + 1) * 128 + n];
    float f2 = W[(k0 + 8) * 128 + n];
    float f3 = W[(k0 + 9) * 128 + n];
    union { __half2 h; unsigned u; } lo, hi;
    lo.h = __float22half2_rn(make_float2(f0, f1));
    hi.h = __float22half2_rn(make_float2(f2, f3));
    g_bw[tid] = make_uint2(lo.u, hi.u);
}

// ---------------- init + dtype detection (fused) ----------------------------
// int64 payloads with values < 2^31 have all odd 32-bit words zero; int32
// payloads essentially never do. Sampled offsets are in-bounds either way.
__global__ void init_k(const int* __restrict__ ei32,
                       const int* __restrict__ b32)
{
    int i = blockIdx.x * blockDim.x + threadIdx.x;
    if (i < NN) { g_dinv[i] = 1.0f; g_cnt[i] = 0; g_fill[i] = 0; }
    if (blockIdx.x == 0) {
        int tid = threadIdx.x;                   // 256 threads
        int je = 1 + 12500 * tid;                // odd words across [1, 2*EE)
        int ei_nz = (ei32[je] != 0);
        int jb = 50001 + 194 * tid;              // odd words, upper half of N
        int b_nz = (b32[jb] != 0);
        int any_ei = __syncthreads_or(ei_nz);
        int any_b  = __syncthreads_or(b_nz);
        if (tid == 0) {
            g_ei_is64 = (any_ei == 0);
            g_b_is64  = (any_b  == 0);
        }
    }
}

// ---------------- edge prep: weighted degree + int in-degree ---------------
__global__ void prep_k(const void* __restrict__ ei,
                       const float* __restrict__ ew) {
    int e = blockIdx.x * blockDim.x + threadIdx.x;
    if (e >= EE) return;
    int c;
    if (g_ei_is64) c = (int)((const long long*)ei)[EE + e];
    else           c = ((const int*)ei)[EE + e];
    atomicAdd(&g_dinv[c], ew[e]);           // weighted in-degree
    atomicAdd(&g_cnt[c], 1);                // integer in-degree (for CSR)
}

// ---------------- exclusive scan of g_cnt -> g_off (+ fused dinv) ----------
#define SCAN_B 512
__global__ void scan1_k() {      // per-block exclusive scan + block totals
    __shared__ int sm[SCAN_B];
    int t = threadIdx.x;
    int idx = blockIdx.x * SCAN_B + t;
    int v = (idx < NN) ? g_cnt[idx] : 0;
    sm[t] = v;
    if (idx < NN) {
        float d = g_dinv[idx];
        g_dinv[idx] = (d > 0.0f) ? rsqrtf(d) : 0.0f;
    }
    __syncthreads();
#pragma unroll
    for (int o = 1; o < SCAN_B; o <<= 1) {
        int x = (t >= o) ? sm[t - o] : 0;
        __syncthreads();
        sm[t] += x;
        __syncthreads();
    }
    if (idx < NN) g_off[idx] = sm[t] - v;        // exclusive
    if (t == SCAN_B - 1) g_bsum[blockIdx.x] = sm[t];
}
__global__ void scan2_k(int nblk) {  // single block: scan block totals
    __shared__ int sm[256];
    int t = threadIdx.x;
    int v = (t < nblk) ? g_bsum[t] : 0;
    sm[t] = v;
    __syncthreads();
#pragma unroll
    for (int o = 1; o < 256; o <<= 1) {
        int x = (t >= o) ? sm[t - o] : 0;
        __syncthreads();
        sm[t] += x;
        __syncthreads();
    }
    if (t < nblk) g_bsum[t] = sm[t] - v;         // exclusive
}
__global__ void scan3_k() {
    int idx = blockIdx.x * SCAN_B + threadIdx.x;
    if (idx < NN) g_off[idx] += g_bsum[blockIdx.x];
    if (idx == 0) g_off[NN] = EE;
}

// ---------------- build sorted adjacency (counting-sort fill) --------------
// decodes edge_index directly (no intermediate row/col arrays)
__global__ void build_k(const void* __restrict__ ei,
                        const float* __restrict__ ew) {
    int e = blockIdx.x * blockDim.x + threadIdx.x;
    if (e >= EE) return;
    int r, c;
    if (g_ei_is64) {
        const long long* p = (const long long*)ei;
        r = (int)p[e]; c = (int)p[EE + e];
    } else {
        const int* p = (const int*)ei;
        r = p[e]; c = p[EE + e];
    }
    int pos = g_off[c] + atomicAdd(&g_fill[c], 1);
    float w = g_dinv[r] * ew[e] * g_dinv[c];
    g_adj[pos] = make_int2(r, __float_as_int(w));
}

// ---------------- tensor-core GEMM: g_th = g_ah[N,128] @ W[128,128] --------
// mma.sync.m16n8k16 (fp16 in, fp32 accum). 256 threads = 8 warps:
// 4 m-warps x 2 n-warps; warp tile m32 x n64. The 128x128 A tile is staged
// once in smem (coalesced uint4, row pitch 136 halfs -> conflict-free LDSM)
// and consumed via ldmatrix.x4. B loads stay coalesced uint2, L1-resident.
__global__ void __launch_bounds__(256, 2)
gemm_tc(int L)
{
    __shared__ __align__(16) __half As[128][136];   // 34.8 KB, pad=8 halfs

    const int tid  = threadIdx.x;
    const int lane = tid & 31;
    const int warp = tid >> 5;
    const int wm = warp & 3;            // 0..3
    const int wn = warp >> 2;           // 0..1
    const int blockrow = blockIdx.x * 128;

    // stage A tile: 128 rows x 16 uint4, fully coalesced
#pragma unroll
    for (int i = tid; i < 128 * 16; i += 256) {
        int row = i >> 4, c16 = i & 15;
        uint4 v = *(const uint4*)(g_ah + (size_t)(blockrow + row) * HH
                                  + c16 * 8);
        *(uint4*)&As[row][c16 * 8] = v;
    }
    __syncthreads();

    const int g  = lane >> 2;           // 0..7
    const int t2 = (lane & 3) * 2;      // 0,2,4,6

    float c0[8][4], c1[8][4];           // two m16 frags x 8 n-tiles
#pragma unroll
    for (int nt = 0; nt < 8; ++nt)
#pragma unroll
        for (int j = 0; j < 4; ++j) { c0[nt][j] = 0.0f; c1[nt][j] = 0.0f; }

    // ldmatrix.x4 lane addressing for an m16k16 A fragment:
    //   lanes 0-15  -> rows 0..15  at col kc*16
    //   lanes 16-31 -> rows 0..15  at col kc*16+8
    const int arow = wm * 32 + (lane & 15);
    const int acol = (lane >> 4) * 8;
    unsigned aaddr0 = (unsigned)__cvta_generic_to_shared(&As[arow][acol]);
    unsigned aaddr1 = (unsigned)__cvta_generic_to_shared(&As[arow + 16][acol]);

    // B base for this lane/warp: [(L*8+kc)*16 + wn*8 + nt]*32 + lane
    const uint2* bbase = g_bw + ((size_t)(L * 8) * 16 + wn * 8) * 32 + lane;

#pragma unroll
    for (int kc = 0; kc < 8; ++kc) {
        unsigned a00, a01, a02, a03, a10, a11, a12, a13;
        asm volatile(
            "ldmatrix.sync.aligned.m8n8.x4.shared.b16 {%0,%1,%2,%3}, [%4];"
            : "=r"(a00), "=r"(a01), "=r"(a02), "=r"(a03)
            : "r"(aaddr0 + kc * 32));
        asm volatile(
            "ldmatrix.sync.aligned.m8n8.x4.shared.b16 {%0,%1,%2,%3}, [%4];"
            : "=r"(a10), "=r"(a11), "=r"(a12), "=r"(a13)
            : "r"(aaddr1 + kc * 32));
        // 8 coalesced uint2 B loads (nt stride = 32 uint2, kc stride = 512)
        const uint2* bp = bbase + (size_t)kc * 16 * 32;
        uint2 b[8];
#pragma unroll
        for (int nt = 0; nt < 8; ++nt) b[nt] = __ldg(bp + (size_t)nt * 32);
#pragma unroll
        for (int nt = 0; nt < 8; ++nt) {
            asm volatile(
                "mma.sync.aligned.m16n8k16.row.col.f32.f16.f16.f32 "
                "{%0,%1,%2,%3}, {%4,%5,%6,%7}, {%8,%9}, {%0,%1,%2,%3};"
                : "+f"(c0[nt][0]), "+f"(c0[nt][1]),
                  "+f"(c0[nt][2]), "+f"(c0[nt][3])
                : "r"(a00), "r"(a01), "r"(a02), "r"(a03),
                  "r"(b[nt].x), "r"(b[nt].y));
            asm volatile(
                "mma.sync.aligned.m16n8k16.row.col.f32.f16.f16.f32 "
                "{%0,%1,%2,%3}, {%4,%5,%6,%7}, {%8,%9}, {%0,%1,%2,%3};"
                : "+f"(c1[nt][0]), "+f"(c1[nt][1]),
                  "+f"(c1[nt][2]), "+f"(c1[nt][3])
                : "r"(a10), "r"(a11), "r"(a12), "r"(a13),
                  "r"(b[nt].x), "r"(b[nt].y));
        }
    }

    // epilogue: fp16 stores (padded g_th -> no bounds checks)
    const size_t r0 = (size_t)(blockrow + wm * 32 + g) * HH;
#pragma unroll
    for (int nt = 0; nt < 8; ++nt) {
        int colb = (wn * 8 + nt) * 8 + t2;
        union { __half2 h; unsigned u; } v;
        v.h = __float22half2_rn(make_float2(c0[nt][0], c0[nt][1]));
        *(unsigned*)(g_th + r0 + colb) = v.u;
        v.h = __float22half2_rn(make_float2(c0[nt][2], c0[nt][3]));
        *(unsigned*)(g_th + r0 + 8 * HH + colb) = v.u;
        v.h = __float22half2_rn(make_float2(c1[nt][0], c1[nt][1]));
        *(unsigned*)(g_th + r0 + 16 * HH + colb) = v.u;
        v.h = __float22half2_rn(make_float2(c1[nt][2], c1[nt][3]));
        *(unsigned*)(g_th + r0 + 24 * HH + colb) = v.u;
    }
}

// ---------------- fused aggregation (gather, no atomics) -------------------
// acc = bias + dinv[n]^2 * th[n] + sum_{e in in(n)} w[e] * th[src[e]]  (fp32)
// g_ah[n] = relu(acc) fp16. One warp per node; lane l owns channels [4l,4l+4).
__global__ void __launch_bounds__(256)
agg_k(const float* __restrict__ bias)
{
    int warp = (blockIdx.x * blockDim.x + threadIdx.x) >> 5;
    if (warp >= NN) return;
    int lane = threadIdx.x & 31;

    float d = g_dinv[warp];
    float s = d * d;
    float4 acc = ((const float4*)bias)[lane];
    {
        uint2 q = *((const uint2*)(g_th + (size_t)warp * HH) + lane);
        float2 f0 = __half22float2(*(const __half2*)&q.x);
        float2 f1 = __half22float2(*(const __half2*)&q.y);
        acc.x = fmaf(f0.x, s, acc.x); acc.y = fmaf(f0.y, s, acc.y);
        acc.z = fmaf(f1.x, s, acc.z); acc.w = fmaf(f1.y, s, acc.w);
    }

    int k   = g_off[warp];
    int end = g_off[warp + 1];

    for (; k + 16 <= end; k += 16) {
        int2 a[16]; uint2 q[16];
#pragma unroll
        for (int u = 0; u < 16; ++u) a[u] = __ldg(&g_adj[k + u]);
#pragma unroll
        for (int u = 0; u < 16; ++u)
            q[u] = __ldg((const uint2*)(g_th + (size_t)a[u].x * HH) + lane);
#pragma unroll
        for (int u = 0; u < 16; ++u) {
            float w = __int_as_float(a[u].y);
            float2 f0 = __half22float2(*(const __half2*)&q[u].x);
            float2 f1 = __half22float2(*(const __half2*)&q[u].y);
            acc.x = fmaf(f0.x, w, acc.x);
            acc.y = fmaf(f0.y, w, acc.y);
            acc.z = fmaf(f1.x, w, acc.z);
            acc.w = fmaf(f1.y, w, acc.w);
        }
    }
    for (; k + 4 <= end; k += 4) {
        int2 a[4]; uint2 q[4];
#pragma unroll
        for (int u = 0; u < 4; ++u) a[u] = __ldg(&g_adj[k + u]);
#pragma unroll
        for (int u = 0; u < 4; ++u)
            q[u] = __ldg((const uint2*)(g_th + (size_t)a[u].x * HH) + lane);
#pragma unroll
        for (int u = 0; u < 4; ++u) {
            float w = __int_as_float(a[u].y);
            float2 f0 = __half22float2(*(const __half2*)&q[u].x);
            float2 f1 = __half22float2(*(const __half2*)&q[u].y);
            acc.x = fmaf(f0.x, w, acc.x);
            acc.y = fmaf(f0.y, w, acc.y);
            acc.z = fmaf(f1.x, w, acc.z);
            acc.w = fmaf(f1.y, w, acc.w);
        }
    }
    for (; k < end; ++k) {
        int2 a = __ldg(&g_adj[k]);
        float w = __int_as_float(a.y);
        uint2 q = __ldg((const uint2*)(g_th + (size_t)a.x * HH) + lane);
        float2 f0 = __half22float2(*(const __half2*)&q.x);
        float2 f1 = __half22float2(*(const __half2*)&q.y);
        acc.x = fmaf(f0.x, w, acc.x); acc.y = fmaf(f0.y, w, acc.y);
        acc.z = fmaf(f1.x, w, acc.z); acc.w = fmaf(f1.y, w, acc.w);
    }

    acc.x = fmaxf(acc.x, 0.0f); acc.y = fmaxf(acc.y, 0.0f);
    acc.z = fmaxf(acc.z, 0.0f); acc.w = fmaxf(acc.w, 0.0f);
    union { __half2 h[2]; uint2 u; } cv;
    cv.h[0] = __float22half2_rn(make_float2(acc.x, acc.y));
    cv.h[1] = __float22half2_rn(make_float2(acc.z, acc.w));
    *((uint2*)(g_ah + (size_t)warp * HH) + lane) = cv.u;
}

// ---------------- two-stage pool + final linear (atomic-free) --------------
__device__ __forceinline__ int lower_bound_batch(const void* batch, int tgt)
{
    int lo = 0, hi = NN;
    while (lo < hi) {
        int mid = (lo + hi) >> 1;
        long long v = g_b_is64 ? ((const long long*)batch)[mid]
                               : (long long)((const int*)batch)[mid];
        if (v < tgt) lo = mid + 1; else hi = mid;
    }
    return lo;
}

// stage 1: 512 blocks = 64 graphs x 8 chunks; partial dot of channel sums
// with lin_w over a row sub-range (linear, so chunk partials sum exactly).
__global__ void pool1_k(const void* __restrict__ batch,
                        const float* __restrict__ lw)
{
    int g  = blockIdx.x >> 3;        // graph
    int ch = blockIdx.x & 7;         // chunk
    int t  = threadIdx.x;            // 128 threads = channel
    __shared__ int se[2];
    if (t == 0) se[0] = lower_bound_batch(batch, g);
    if (t == 1) se[1] = lower_bound_batch(batch, g + 1);
    __syncthreads();
    int s = se[0], len = se[1] - se[0];
    int c0 = s + (int)(((long long)len * ch) >> 3);
    int c1 = s + (int)(((long long)len * (ch + 1)) >> 3);

    float sum = 0.0f;
    int r = c0;
    for (; r + 4 <= c1; r += 4) {
        sum += __half2float(g_ah[(size_t)(r + 0) * HH + t]);
        sum += __half2float(g_ah[(size_t)(r + 1) * HH + t]);
        sum += __half2float(g_ah[(size_t)(r + 2) * HH + t]);
        sum += __half2float(g_ah[(size_t)(r + 3) * HH + t]);
    }
    for (; r < c1; ++r)
        sum += __half2float(g_ah[(size_t)r * HH + t]);

    float v = sum * lw[t];
#pragma unroll
    for (int o = 16; o > 0; o >>= 1)
        v += __shfl_down_sync(0xffffffffu, v, o);
    __shared__ float sm[4];
    if ((t & 31) == 0) sm[t >> 5] = v;
    __syncthreads();
    if (t == 0) g_part[blockIdx.x] = sm[0] + sm[1] + sm[2] + sm[3];
}

// stage 2: combine chunk partials, divide by node count, add bias.
__global__ void final_k(const void* __restrict__ batch,
                        const float* __restrict__ lb,
                        float* __restrict__ out)
{
    int g = threadIdx.x;             // 64 threads
    if (g >= GG) return;
    int s = lower_bound_batch(batch, g);
    int e = lower_bound_batch(batch, g + 1);
    float sum = 0.0f;
#pragma unroll
    for (int c = 0; c < PCH; ++c) sum += g_part[g * PCH + c];
    out[g] = sum / fmaxf((float)(e - s), 1.0f) + lb[0];
}

// ---------------- launcher --------------------------------------------------
extern "C" void kernel_launch(void* const* d_in, const int* in_sizes, int n_in,
                              void* d_out, int out_size)
{
    // Locate inputs by element count (robust to metadata ordering).
    const float* x = nullptr;
    const float* ew = nullptr;
    const void*  ei = nullptr;     // int32 or int64 (auto-detected on device)
    const void*  batch = nullptr;  // int32 or int64
    const float* Wm[3] = {nullptr, nullptr, nullptr};
    const float* v128[4] = {nullptr, nullptr, nullptr, nullptr}; // b1,b2,b3,lin_w
    const float* linb = nullptr;
    int wi = 0, bi = 0;
    for (int i = 0; i < n_in; ++i) {
        int s = in_sizes[i];
        if      (s == NN * HH)  x = (const float*)d_in[i];
        else if (s == EE)       ew = (const float*)d_in[i];
        else if (s == 2 * EE)   ei = d_in[i];
        else if (s == NN)       batch = d_in[i];
        else if (s == HH * HH)  { if (wi < 3) Wm[wi++] = (const float*)d_in[i]; }
        else if (s == HH)       { if (bi < 4) v128[bi++] = (const float*)d_in[i]; }
        else if (s == 1)        linb = (const float*)d_in[i];
    }
    const float* lw = v128[3];
    float* out = (float*)d_out;

    // Side stream + fork/join events (created once; streams/events are not
    // device-memory allocations). Non-blocking stream avoids legacy-stream
    // implicit serialization; fork/join events make the capture a valid DAG.
    static cudaStream_t s2 = nullptr;
    static cudaEvent_t evFork = nullptr, evJoin = nullptr;
    if (!s2) {
        cudaStreamCreateWithFlags(&s2, cudaStreamNonBlocking);
        cudaEventCreateWithFlags(&evFork, cudaEventDisableTiming);
        cudaEventCreateWithFlags(&evJoin, cudaEventDisableTiming);
    }

    const int TB = 256;
    const int gN  = (NN + TB - 1) / TB;
    const int gE  = (EE + TB - 1) / TB;
    const int gCv = (NN * HH / 8 + TB - 1) / TB;
    const int gAg = (int)(((long long)NN * 32 + TB - 1) / TB);  // warp/node
    const int gGm = (NN + 127) / 128;                           // 782
    const int nScanBlk = (NN + SCAN_B - 1) / SCAN_B;            // 196

    // Fork: chain B (CSR preprocessing) runs on s2 concurrently with
    // chain A (cvtx + repack + layer-1 GEMM) on the capture stream.
    cudaEventRecord(evFork, 0);
    cudaStreamWaitEvent(s2, evFork, 0);

    // Chain B (side stream): init -> prep -> scan -> build
    init_k<<<gN, TB, 0, s2>>>((const int*)ei, (const int*)batch);
    prep_k<<<gE, TB, 0, s2>>>(ei, ew);
    scan1_k<<<nScanBlk, SCAN_B, 0, s2>>>();           // scan + dinv
    scan2_k<<<1, 256, 0, s2>>>(nScanBlk);
    scan3_k<<<nScanBlk, SCAN_B, 0, s2>>>();
    build_k<<<gE, TB, 0, s2>>>(ei, ew);
    cudaEventRecord(evJoin, s2);

    // Chain A (capture stream): x->fp16, W repack, layer-1 GEMM
    cvtx_k<<<gCv, TB>>>(x);
    repack_k<<<48, 256>>>(Wm[0], Wm[1], Wm[2]);
    gemm_tc<<<gGm, TB>>>(0);                   // th = x @ W1

    // Join: aggregation needs both chains
    cudaStreamWaitEvent(0, evJoin, 0);

    // Layer 1 aggregation: ah = relu(b1 + dinv^2*th + gather(th))
    agg_k<<<gAg, TB>>>(v128[0]);

    // Layer 2
    gemm_tc<<<gGm, TB>>>(1);
    agg_k<<<gAg, TB>>>(v128[1]);

    // Layer 3
    gemm_tc<<<gGm, TB>>>(2);
    agg_k<<<gAg, TB>>>(v128[2]);

    // Two-stage pool + final linear
    pool1_k<<<GG * PCH, 128>>>(batch, lw);
    final_k<<<1, 64>>>(batch, linb, out);
}